// round 16
// baseline (speedup 1.0000x reference)
#include <cuda_runtime.h>

// ---------------- problem constants (fixed for this dataset) ----------------
#define Zl    384
#define MBr   46
#define DEGc  7
#define NBc   68
#define BEe   (MBr*DEGc)      // 322 base edges
#define NLD   (NBc*Zl)        // 26112 variable nodes
#define MCK   (MBr*Zl)        // 17664 check nodes
#define EDG   (BEe*Zl)        // 123648 edges
#define BATCH 128
#define B4    32              // batch in float4 units (array stride)
#define B4Q   4               // per-chain float4 slots (batch 16)
#define NCH   8               // chains (2 per stream, 4 streams)
#define NST   4               // streams (main + 3 created: proven-safe budget)
#define KI    8448            // info bits out  (= 22*Zl)
#define KCOLS 22              // info base columns
#define NIN   25344           // received LLRs per batch row
#define NITER 20
#define LLRMAX 20.0f

// ---------------- static device scratch (no allocations allowed) ------------
// Single in-place edge message buffer: holds m_vc before k_cn, m_cv after.
// Footprint: 63.3 + 13.4 = ~77MB  -> resident in 126MB L2.
__device__ float4   g_msg[EDG*B4];      // edge messages (in-place)  63.3MB
__device__ float4   g_lch[NLD*B4];      // channel LLR (-clip)       13.4MB
__device__ unsigned g_bec[BEe];         // per base-edge: (c<<10)|shift
__device__ unsigned g_colptr[NBc+1];    // CSR over base columns
__device__ unsigned g_colent[BEe];      // (base_edge<<10)|shift

// ---------------- graph decode + CSR build (parallel, once per launch) ------
__global__ void k_build(const int* __restrict__ col) {
    __shared__ unsigned bec[BEe];
    int t = threadIdx.x;                 // 512 threads
    if (t < BEe) {
        int val = col[t * Zl];           // i=0 edge of this base-edge block
        unsigned u = ((unsigned)(val / Zl) << 10) | (unsigned)(val % Zl);
        bec[t] = u;
        g_bec[t] = u;
    }
    __syncthreads();
    if (t < NBc) {
        unsigned tc = (unsigned)t;
        unsigned off = 0, cnt = 0;
        for (int e = 0; e < BEe; e++) {
            unsigned c = bec[e] >> 10;
            off += (c < tc);
            cnt += (c == tc);
        }
        g_colptr[t] = off;
        if (t == NBc - 1) g_colptr[NBc] = off + cnt;
        unsigned pos = off;
        for (int e = 0; e < BEe; e++)
            if ((bec[e] >> 10) == tc)
                g_colent[pos++] = ((unsigned)e << 10) | (bec[e] & 1023u);
    }
}

// Per-chain channel-LLR slice: transpose + clip + negate 16 batch rows into
// lch[(768+n)*128 + (bbase+..)], plus zero-fill of the punctured region
// (vars [0,768)) for this chain's 4 float4 slots. ofs = chain's float4 base.
__global__ void k_lch(const float* __restrict__ llr, int ofs) {
    __shared__ float tile[32][17];
    float* lch = (float*)g_lch;
    int bx = blockIdx.x;
    int tx = threadIdx.x, ty = threadIdx.y;          // block (32, 8)
    int bbase = 4 * ofs;                             // first batch element
    if (bx >= NIN / 32) {
        // zero region: 768 vars x 4 float4 slots = 3072 float4 = 3 blocks x 1024
        int t = (bx - NIN / 32) * 1024 + ty * 128 + tx * 4;
#pragma unroll
        for (int j = 0; j < 4; j++) {
            int idx = t + j;                         // [0, 3072)
            int v   = idx >> 2;
            int sl  = idx & 3;
            g_lch[v * B4 + ofs + sl] = make_float4(0.f, 0.f, 0.f, 0.f);
        }
        return;
    }
    int n0 = bx * 32;
    // load 16 batch rows x 32 vars (two rows per ty)
#pragma unroll
    for (int k = 0; k < 2; k++)
        tile[tx][ty + k*8] = llr[(size_t)(bbase + ty + k*8) * NIN + (n0 + tx)];
    __syncthreads();
    // write transposed: 32 vars x 16 batch
#pragma unroll
    for (int k = 0; k < 4; k++) {
        int n = ty + k * 8;                          // var within tile [0,32)
        int b = tx & 15;                             // batch slot [0,16)
        if (tx < 16) {
            float v = tile[n][b];
            v = fminf(fmaxf(v, -LLRMAX), LLRMAX);
            lch[(size_t)(768 + n0 + n) * BATCH + (bbase + b)] = -v;
        }
    }
}

// ---------------- check-node update (min-sum, exclude-self) -----------------
// Branchless. Tie handling matches reference first-argmin exactly: on a tie
// m2 == m1, so (mag==m1 ? m2 : m1) gives the same value either way.
#define CNCOMP(F)                                                              \
    {                                                                          \
        float m1 = fabsf(v[0].F), m2 = 1e30f;                                  \
        unsigned par = __float_as_uint(v[0].F);                                \
        _Pragma("unroll")                                                      \
        for (int d = 1; d < DEGc; d++) {                                       \
            float mag = fabsf(v[d].F);                                         \
            m2 = fminf(m2, fmaxf(m1, mag));                                    \
            m1 = fminf(m1, mag);                                               \
            par ^= __float_as_uint(v[d].F);                                    \
        }                                                                      \
        par &= 0x80000000u;                                                    \
        _Pragma("unroll")                                                      \
        for (int d = 0; d < DEGc; d++) {                                       \
            unsigned bits = __float_as_uint(v[d].F);                           \
            float mag = fabsf(v[d].F);                                         \
            float sel = (mag == m1) ? m2 : m1;                                 \
            unsigned s = (par ^ bits) & 0x80000000u;                           \
            v[d].F = __uint_as_float(__float_as_uint(sel) | s);                \
        }                                                                      \
    }

template<bool FIRST, bool LASTCN>
__global__ void __launch_bounds__(256) k_cn(int ofs) {
    int tid = blockIdx.x * 256 + threadIdx.x;    // MCK*B4Q = 70656 = 276*256
    int b4 = (tid & (B4Q - 1)) + ofs;            // batch slot within chain
    int m  = tid >> 2;                           // check index
    int r  = m / Zl;
    int i  = m - r * Zl;
    int beb  = r * DEGc;
    int base = (beb * Zl + i) * B4 + b4;

    float4 v[DEGc];
    if (FIRST) {
        // iteration 0: m_cv == 0 so m_vc == lch[col]; gather channel LLRs
#pragma unroll
        for (int d = 0; d < DEGc; d++) {
            unsigned u = g_bec[beb + d];
            int c  = (int)(u >> 10);
            int sh = (int)(u & 1023u);
            int iv = i + sh; if (iv >= Zl) iv -= Zl;
            v[d] = __ldg(&g_lch[(c * Zl + iv) * B4 + b4]);
        }
    } else {
        // steady state: m_vc stored contiguously (in place) by the VN kernel
#pragma unroll
        for (int d = 0; d < DEGc; d++)
            v[d] = g_msg[base + d * (Zl * B4)];
    }

    CNCOMP(x) CNCOMP(y) CNCOMP(z) CNCOMP(w)

    // in-place overwrite: buffer now holds m_cv. On the last iteration only
    // edges feeding info base-columns (<22) are consumed downstream.
#pragma unroll
    for (int d = 0; d < DEGc; d++) {
        if (LASTCN && (g_bec[beb + d] >> 10) >= KCOLS) continue;
        g_msg[base + d * (Zl * B4)] = v[d];
    }
}

// ---------------- variable-node update: m_vc = acc - m_cv, in place ---------
__global__ void __launch_bounds__(256) k_vn(int ofs) {
    int tid = blockIdx.x * 256 + threadIdx.x;    // NLD*B4Q = 104448 = 408*256
    int b4 = (tid & (B4Q - 1)) + ofs;
    int v  = tid >> 2;
    int c  = v / Zl;
    int i  = v - c * Zl;
    float4 acc = g_lch[v * B4 + b4];
    unsigned j0 = g_colptr[c], j1 = g_colptr[c + 1];
    // pass 1: accumulate total (each 4-lane group reads 64B = 2 sectors/edge)
    for (unsigned j = j0; j < j1; j++) {
        unsigned u = g_colent[j];
        int be = (int)(u >> 10);
        int sh = (int)(u & 1023u);
        int ic = i - sh; if (ic < 0) ic += Zl;
        float4 t = __ldg(&g_msg[(be * Zl + ic) * B4 + b4]);
        acc.x += t.x; acc.y += t.y; acc.z += t.z; acc.w += t.w;
    }
    // pass 2: reload (L1-hot) and overwrite with extrinsic VN->CN messages
    for (unsigned j = j0; j < j1; j++) {
        unsigned u = g_colent[j];
        int be = (int)(u >> 10);
        int sh = (int)(u & 1023u);
        int ic = i - sh; if (ic < 0) ic += Zl;
        int idx = (be * Zl + ic) * B4 + b4;
        float4 t = __ldg(&g_msg[idx]);
        g_msg[idx] = make_float4(acc.x - t.x, acc.y - t.y,
                                 acc.z - t.z, acc.w - t.w);
    }
}

// ---------------- fused finale: final VN total + transpose + negate ---------
// Per chain: computes x = lch + sum(m_cv) for info vars only and writes
// out[b*KI+n] = -x directly (identical fp32 sum order to k_vn pass 1).
__global__ void k_fin(int ofs, float* __restrict__ out) {
    __shared__ float tile[16][33];
    int n0 = blockIdx.x * 32;                    // KI/32 = 264 blocks
    int tx = threadIdx.x, ty = threadIdx.y;      // block (32, 4)
    int v  = n0 + tx;                            // info var (< KI)
    int b4 = ofs + ty;                           // chain's float4 slot
    int c  = v / Zl;
    int i  = v - c * Zl;
    float4 acc = g_lch[v * B4 + b4];
    unsigned j0 = g_colptr[c], j1 = g_colptr[c + 1];
    for (unsigned j = j0; j < j1; j++) {
        unsigned u = g_colent[j];
        int be = (int)(u >> 10);
        int sh = (int)(u & 1023u);
        int ic = i - sh; if (ic < 0) ic += Zl;
        float4 t = __ldg(&g_msg[(be * Zl + ic) * B4 + b4]);
        acc.x += t.x; acc.y += t.y; acc.z += t.z; acc.w += t.w;
    }
    tile[4*ty + 0][tx] = acc.x;
    tile[4*ty + 1][tx] = acc.y;
    tile[4*ty + 2][tx] = acc.z;
    tile[4*ty + 3][tx] = acc.w;
    __syncthreads();
    int bbase = 4 * ofs;                         // chain's first batch element
#pragma unroll
    for (int k = 0; k < 4; k++) {
        int bl = ty + 4 * k;                     // batch-local [0,16)
        out[(size_t)(bbase + bl) * KI + n0 + tx] = -tile[bl][tx];
    }
}

// ---------------- launch: 8 chains, 2 per stream, launches interleaved ------
#define CN_GRID  ((MCK * B4Q) / 256)
#define VN_GRID  ((NLD * B4Q) / 256)

static void run_pair(cudaStream_t s, int ofsA, int ofsB,
                     const float* llr, float* out) {
    dim3 gl(NIN / 32 + 3), bl(32, 8);
    k_lch<<<gl, bl, 0, s>>>(llr, ofsA);
    k_lch<<<gl, bl, 0, s>>>(llr, ofsB);
    k_cn<true, false><<<CN_GRID, 256, 0, s>>>(ofsA);
    k_cn<true, false><<<CN_GRID, 256, 0, s>>>(ofsB);
    k_vn<<<VN_GRID, 256, 0, s>>>(ofsA);
    k_vn<<<VN_GRID, 256, 0, s>>>(ofsB);
    for (int it = 1; it < NITER - 1; it++) {
        k_cn<false, false><<<CN_GRID, 256, 0, s>>>(ofsA);
        k_cn<false, false><<<CN_GRID, 256, 0, s>>>(ofsB);
        k_vn<<<VN_GRID, 256, 0, s>>>(ofsA);
        k_vn<<<VN_GRID, 256, 0, s>>>(ofsB);
    }
    k_cn<false, true><<<CN_GRID, 256, 0, s>>>(ofsA);
    k_cn<false, true><<<CN_GRID, 256, 0, s>>>(ofsB);
    dim3 gf(KI / 32), bf(32, 4);
    k_fin<<<gf, bf, 0, s>>>(ofsA, out);
    k_fin<<<gf, bf, 0, s>>>(ofsB, out);
}

extern "C" void kernel_launch(void* const* d_in, const int* in_sizes, int n_in,
                              void* d_out, int out_size) {
    const float* llr = (const float*)d_in[0];
    const int*   col = (const int*)d_in[2];
    float*       out = (float*)d_out;

    // host-side infra objects, created once on the (non-captured) first call.
    // NST-1 = 3 created streams: same budget as the passing R14 config.
    static cudaStream_t st[NST - 1] = {};
    static cudaEvent_t  evBld = 0;
    static cudaEvent_t  evJoin[NST - 1] = {};
    static bool tried = false, ok = false;
    if (!tried) {
        tried = true;
        ok = true;
        for (int k = 0; k < NST - 1; k++)
            if (cudaStreamCreateWithFlags(&st[k], cudaStreamNonBlocking) != cudaSuccess) ok = false;
        if (cudaEventCreateWithFlags(&evBld, cudaEventDisableTiming) != cudaSuccess) ok = false;
        for (int k = 0; k < NST - 1; k++)
            if (cudaEventCreateWithFlags(&evJoin[k], cudaEventDisableTiming) != cudaSuccess) ok = false;
    }

    if (ok) {
        // graph build first (tiny); pairs fork off it. Each chain produces
        // its own lch slice, so no full-batch serialization at the head.
        k_build<<<1, 512>>>(col);
        cudaEventRecord(evBld, 0);
        for (int k = 0; k < NST - 1; k++)
            cudaStreamWaitEvent(st[k], evBld, 0);
        // stream 0 (main): chains 0,4 ; stream k: chains k, k+4
        run_pair(0, 0, 4 * B4Q, llr, out);
        for (int k = 0; k < NST - 1; k++)
            run_pair(st[k], (k + 1) * B4Q, (k + 5) * B4Q, llr, out);
        for (int k = 0; k < NST - 1; k++) {
            cudaEventRecord(evJoin[k], st[k]);
            cudaStreamWaitEvent(0, evJoin[k], 0);
        }
    } else {
        k_build<<<1, 512>>>(col);
        for (int k = 0; k < NCH; k++) {
            dim3 gl(NIN / 32 + 3), bl(32, 8);
            k_lch<<<gl, bl>>>(llr, k * B4Q);
        }
        for (int k = 0; k < NCH; k += 2)
            run_pair(0, k * B4Q, (k + 1) * B4Q, llr, out);
    }
}

// round 17
// speedup vs baseline: 1.7320x; 1.7320x over previous
#include <cuda_runtime.h>

// ---------------- problem constants (fixed for this dataset) ----------------
#define Zl    384
#define MBr   46
#define DEGc  7
#define NBc   68
#define BEe   (MBr*DEGc)      // 322 base edges
#define NLD   (NBc*Zl)        // 26112 variable nodes
#define MCK   (MBr*Zl)        // 17664 check nodes
#define EDG   (BEe*Zl)        // 123648 edges
#define BATCH 128
#define B4    32              // batch in float4 units (array stride)
#define B4Q   8               // per-chain float4 slots (batch 32)
#define NCH   4               // chains
#define KI    8448            // info bits out  (= 22*Zl)
#define KCOLS 22              // info base columns
#define NIN   25344           // received LLRs per batch row
#define NITER 20
#define LLRMAX 20.0f

// ---------------- static device scratch (no allocations allowed) ------------
// Single in-place edge message buffer: holds m_vc before k_cn, m_cv after.
// Footprint: 63.3 + 13.4 = ~77MB  -> resident in 126MB L2.
__device__ float4   g_msg[EDG*B4];      // edge messages (in-place)  63.3MB
__device__ float4   g_lch[NLD*B4];      // channel LLR (-clip)       13.4MB
__device__ unsigned g_bec[BEe];         // per base-edge: (c<<10)|shift
__device__ unsigned g_colptr[NBc+1];    // CSR over base columns
__device__ unsigned g_colent[BEe];      // (base_edge<<10)|shift

// ---------------- graph decode + CSR build (parallel, once per launch) ------
__global__ void k_build(const int* __restrict__ col) {
    __shared__ unsigned bec[BEe];
    int t = threadIdx.x;                 // 512 threads
    if (t < BEe) {
        int val = col[t * Zl];           // i=0 edge of this base-edge block
        unsigned u = ((unsigned)(val / Zl) << 10) | (unsigned)(val % Zl);
        bec[t] = u;
        g_bec[t] = u;
    }
    __syncthreads();
    if (t < NBc) {
        unsigned tc = (unsigned)t;
        unsigned off = 0, cnt = 0;
        for (int e = 0; e < BEe; e++) {
            unsigned c = bec[e] >> 10;
            off += (c < tc);
            cnt += (c == tc);
        }
        g_colptr[t] = off;
        if (t == NBc - 1) g_colptr[NBc] = off + cnt;
        unsigned pos = off;
        for (int e = 0; e < BEe; e++)
            if ((bec[e] >> 10) == tc)
                g_colent[pos++] = ((unsigned)e << 10) | (bec[e] & 1023u);
    }
}

// Per-chain channel-LLR slice: transpose + clip + negate 32 batch rows into
// lch[(768+n)*128 + (bbase+tx)], plus zero-fill of the punctured region
// (vars [0,768)) for this chain's 8 float4 slots. ofs = chain's float4 base.
__global__ void k_lch(const float* __restrict__ llr, int ofs) {
    __shared__ float tile[32][33];
    float* lch = (float*)g_lch;
    int bx = blockIdx.x;
    int tx = threadIdx.x, ty = threadIdx.y;          // block (32, 8)
    int bbase = 4 * ofs;                             // first batch element
    if (bx >= NIN / 32) {
        // zero region: 768 vars x 8 float4 slots = 6144 float4 = 6 blocks x 1024
        int t = (bx - NIN / 32) * 1024 + ty * 128 + tx * 4;
#pragma unroll
        for (int j = 0; j < 4; j++) {
            int idx = t + j;                         // [0, 6144)
            int v   = idx >> 3;
            int sl  = idx & 7;
            g_lch[v * B4 + ofs + sl] = make_float4(0.f, 0.f, 0.f, 0.f);
        }
        return;
    }
    int n0 = bx * 32;
#pragma unroll
    for (int k = 0; k < 4; k++)
        tile[ty + k*8][tx] = llr[(size_t)(bbase + ty + k*8) * NIN + (n0 + tx)];
    __syncthreads();
#pragma unroll
    for (int k = 0; k < 4; k++) {
        float v = tile[tx][ty + k*8];
        v = fminf(fmaxf(v, -LLRMAX), LLRMAX);
        lch[(size_t)(768 + n0 + ty + k*8) * BATCH + (bbase + tx)] = -v;
    }
}

// ---------------- check-node update (min-sum, exclude-self) -----------------
// Branchless. Tie handling matches reference first-argmin exactly: on a tie
// m2 == m1, so (mag==m1 ? m2 : m1) gives the same value either way.
#define CNCOMP(F)                                                              \
    {                                                                          \
        float m1 = fabsf(v[0].F), m2 = 1e30f;                                  \
        unsigned par = __float_as_uint(v[0].F);                                \
        _Pragma("unroll")                                                      \
        for (int d = 1; d < DEGc; d++) {                                       \
            float mag = fabsf(v[d].F);                                         \
            m2 = fminf(m2, fmaxf(m1, mag));                                    \
            m1 = fminf(m1, mag);                                               \
            par ^= __float_as_uint(v[d].F);                                    \
        }                                                                      \
        par &= 0x80000000u;                                                    \
        _Pragma("unroll")                                                      \
        for (int d = 0; d < DEGc; d++) {                                       \
            unsigned bits = __float_as_uint(v[d].F);                           \
            float mag = fabsf(v[d].F);                                         \
            float sel = (mag == m1) ? m2 : m1;                                 \
            unsigned s = (par ^ bits) & 0x80000000u;                           \
            v[d].F = __uint_as_float(__float_as_uint(sel) | s);                \
        }                                                                      \
    }

template<bool FIRST, bool LASTCN>
__global__ void __launch_bounds__(256) k_cn(int ofs) {
    int tid = blockIdx.x * 256 + threadIdx.x;    // MCK*B4Q = 141312 = 552*256
    int b4 = (tid & (B4Q - 1)) + ofs;            // batch slot within chain
    int m  = tid >> 3;                           // check index
    int r  = m / Zl;
    int i  = m - r * Zl;
    int beb  = r * DEGc;
    int base = (beb * Zl + i) * B4 + b4;

    float4 v[DEGc];
    if (FIRST) {
        // iteration 0: m_cv == 0 so m_vc == lch[col]; gather channel LLRs
#pragma unroll
        for (int d = 0; d < DEGc; d++) {
            unsigned u = g_bec[beb + d];
            int c  = (int)(u >> 10);
            int sh = (int)(u & 1023u);
            int iv = i + sh; if (iv >= Zl) iv -= Zl;
            v[d] = __ldg(&g_lch[(c * Zl + iv) * B4 + b4]);
        }
    } else {
        // steady state: m_vc stored contiguously (in place) by the VN kernel
#pragma unroll
        for (int d = 0; d < DEGc; d++)
            v[d] = g_msg[base + d * (Zl * B4)];
    }

    CNCOMP(x) CNCOMP(y) CNCOMP(z) CNCOMP(w)

    // in-place overwrite: buffer now holds m_cv. On the last iteration only
    // edges feeding info base-columns (<22) are consumed downstream.
#pragma unroll
    for (int d = 0; d < DEGc; d++) {
        if (LASTCN && (g_bec[beb + d] >> 10) >= KCOLS) continue;
        g_msg[base + d * (Zl * B4)] = v[d];
    }
}

// ---------------- variable-node update: m_vc = acc - m_cv, in place ---------
__global__ void __launch_bounds__(256) k_vn(int ofs) {
    int tid = blockIdx.x * 256 + threadIdx.x;    // NLD*B4Q = 208896 = 816*256
    int b4 = (tid & (B4Q - 1)) + ofs;
    int v  = tid >> 3;
    int c  = v / Zl;
    int i  = v - c * Zl;
    float4 acc = g_lch[v * B4 + b4];
    unsigned j0 = g_colptr[c], j1 = g_colptr[c + 1];
    // pass 1: accumulate total (each 8-lane group reads one 128B line per edge)
    for (unsigned j = j0; j < j1; j++) {
        unsigned u = g_colent[j];
        int be = (int)(u >> 10);
        int sh = (int)(u & 1023u);
        int ic = i - sh; if (ic < 0) ic += Zl;
        float4 t = __ldg(&g_msg[(be * Zl + ic) * B4 + b4]);
        acc.x += t.x; acc.y += t.y; acc.z += t.z; acc.w += t.w;
    }
    // pass 2: reload (L1-hot) and overwrite with extrinsic VN->CN messages
    for (unsigned j = j0; j < j1; j++) {
        unsigned u = g_colent[j];
        int be = (int)(u >> 10);
        int sh = (int)(u & 1023u);
        int ic = i - sh; if (ic < 0) ic += Zl;
        int idx = (be * Zl + ic) * B4 + b4;
        float4 t = __ldg(&g_msg[idx]);
        g_msg[idx] = make_float4(acc.x - t.x, acc.y - t.y,
                                 acc.z - t.z, acc.w - t.w);
    }
}

// ---------------- fused finale: final VN total + transpose + negate ---------
// Per chain: computes x = lch + sum(m_cv) for info vars only and writes
// out[b*KI+n] = -x directly (identical fp32 sum order to k_vn pass 1).
__global__ void k_fin(int ofs, float* __restrict__ out) {
    __shared__ float tile[32][33];
    int n0 = blockIdx.x * 32;                    // KI/32 = 264 blocks
    int tx = threadIdx.x, ty = threadIdx.y;      // block (32, 8)
    int v  = n0 + tx;                            // info var (< KI)
    int b4 = ofs + ty;                           // chain's float4 slot
    int c  = v / Zl;
    int i  = v - c * Zl;
    float4 acc = g_lch[v * B4 + b4];
    unsigned j0 = g_colptr[c], j1 = g_colptr[c + 1];
    for (unsigned j = j0; j < j1; j++) {
        unsigned u = g_colent[j];
        int be = (int)(u >> 10);
        int sh = (int)(u & 1023u);
        int ic = i - sh; if (ic < 0) ic += Zl;
        float4 t = __ldg(&g_msg[(be * Zl + ic) * B4 + b4]);
        acc.x += t.x; acc.y += t.y; acc.z += t.z; acc.w += t.w;
    }
    tile[4*ty + 0][tx] = acc.x;
    tile[4*ty + 1][tx] = acc.y;
    tile[4*ty + 2][tx] = acc.z;
    tile[4*ty + 3][tx] = acc.w;
    __syncthreads();
    int bbase = 4 * ofs;                         // chain's first batch element
#pragma unroll
    for (int k = 0; k < 4; k++) {
        int bl = ty + 8 * k;
        out[(size_t)(bbase + bl) * KI + n0 + tx] = -tile[bl][tx];
    }
}

// ---------------- launch: four independent batch chains on forked streams ---
static void run_chain(cudaStream_t s, int ofs, const float* llr, float* out) {
    // per-chain channel slice (transpose 32 batch rows + zero punctured slice)
    {
        dim3 g(NIN / 32 + 6), b(32, 8);
        k_lch<<<g, b, 0, s>>>(llr, ofs);
    }
    k_cn<true, false><<<(MCK * B4Q) / 256, 256, 0, s>>>(ofs);
    k_vn<<<(NLD * B4Q) / 256, 256, 0, s>>>(ofs);
    for (int it = 1; it < NITER - 1; it++) {
        k_cn<false, false><<<(MCK * B4Q) / 256, 256, 0, s>>>(ofs);
        k_vn<<<(NLD * B4Q) / 256, 256, 0, s>>>(ofs);
    }
    k_cn<false, true><<<(MCK * B4Q) / 256, 256, 0, s>>>(ofs);
    // fused finale: final totals for info vars -> transpose -> d_out
    {
        dim3 g(KI / 32), b(32, 8);
        k_fin<<<g, b, 0, s>>>(ofs, out);
    }
}

extern "C" void kernel_launch(void* const* d_in, const int* in_sizes, int n_in,
                              void* d_out, int out_size) {
    const float* llr = (const float*)d_in[0];
    const int*   col = (const int*)d_in[2];
    float*       out = (float*)d_out;

    // host-side infra objects, created once on the (non-captured) first call
    static cudaStream_t st[NCH - 1] = {};
    static cudaEvent_t  evBld = 0;
    static cudaEvent_t  evJoin[NCH - 1] = {};
    static bool tried = false, ok = false;
    if (!tried) {
        tried = true;
        ok = true;
        for (int k = 0; k < NCH - 1; k++)
            if (cudaStreamCreateWithFlags(&st[k], cudaStreamNonBlocking) != cudaSuccess) ok = false;
        if (cudaEventCreateWithFlags(&evBld, cudaEventDisableTiming) != cudaSuccess) ok = false;
        for (int k = 0; k < NCH - 1; k++)
            if (cudaEventCreateWithFlags(&evJoin[k], cudaEventDisableTiming) != cudaSuccess) ok = false;
    }

    if (ok) {
        // graph build first (tiny); chains fork off it. Each chain produces
        // its own lch slice, so no full-batch serialization at the head.
        k_build<<<1, 512>>>(col);
        cudaEventRecord(evBld, 0);
        for (int k = 0; k < NCH - 1; k++)
            cudaStreamWaitEvent(st[k], evBld, 0);
        run_chain(0, 0, llr, out);                     // chain 0 on main stream
        for (int k = 0; k < NCH - 1; k++)
            run_chain(st[k], (k + 1) * B4Q, llr, out); // chains 1..3
        for (int k = 0; k < NCH - 1; k++) {
            cudaEventRecord(evJoin[k], st[k]);
            cudaStreamWaitEvent(0, evJoin[k], 0);
        }
    } else {
        k_build<<<1, 512>>>(col);
        for (int k = 0; k < NCH; k++)
            run_chain(0, k * B4Q, llr, out);
    }
}